// round 16
// baseline (speedup 1.0000x reference)
#include <cuda_runtime.h>
#include <math.h>
#include <float.h>

#define RES   512
#define HID   128
#define NSEG  (HID + 1)            // 129 outer segments
#define SLOT  130                  // fixed slots per outer segment (padded layout)
#define KTOT  (NSEG * SLOT)        // 16770 padded final segments (fits uint16)
#define CAP   4096                 // compact-table capacity (expected K ~ 300-1500)
#define ROWS_PER_QB 4
#define QROWB ((RES - 1 + ROWS_PER_QB - 1) / ROWS_PER_QB)   // 128 row-blocks/plane
#define QBLOCKS (3 * QROWB)        // 384 quad-builder blocks

// ---- linear LUT over F in [LUT_LO, LUT_HI), 8192 bins + edge slack ----
#define NB      8192
#define LUT_LO  (-8.0f)
#define LUT_HI  ( 8.0f)
#define LSCALE  512.0f             // NB / (HI - LO)
#define LUTE    (NB + 3)           // slut entries e = 0..NB+2, edge(e)=LO+(e-1)/LSCALE

#define SENTINEL_BITS 0x7FC00000u  // quiet NaN pattern, tested bitwise

// ---------------- persistent device tables (rebuilt every launch) ----------
__device__ float  g_flatT[KTOT];            // padded non-decreasing breakpoints
__device__ float2 g_flatAB[KTOT];           // padded (A, B+b3)
__device__ int    g_m[NSEG];                // # inner kinks per outer segment
__device__ int    g_K;                      // compact count
__device__ float  g_cT[CAP];                // compact breakpoints
__device__ float2 g_cAB[CAP];               // compact coefficients
__device__ float2 g_lutAB2[NB + 2];         // direct-answer LUT (or sentinel+bounds)
__device__ unsigned short g_lut[LUTE];      // only used on the K>CAP fallback path
__device__ float4 g_quad[3 * 512 * 512];    // 2x2 corner quads per plane (12MB)

// ============================================================================
// Fused setup: blocks [0,129) build padded PWL tables + counts; blocks
// [129,129+384) build the quad layout, 4 quad-rows per block.
// ============================================================================
__global__ void setup_all(const float* __restrict__ w1,
                          const float* __restrict__ b1,
                          const float* __restrict__ w2,
                          const float* __restrict__ b2,
                          const float* __restrict__ w3,
                          const float* __restrict__ b3,
                          const float* __restrict__ xy,
                          const float* __restrict__ yz,
                          const float* __restrict__ xz) {
    int t = threadIdx.x;

    if (blockIdx.x >= NSEG) {
        // ---------------- quad builder: 4 rows per block ----------------
        int b = blockIdx.x - NSEG;
        int p = b / QROWB;
        int i0 = (b % QROWB) * ROWS_PER_QB;
        const float* pl = (p == 0) ? xy : (p == 1) ? yz : xz;

        float a[ROWS_PER_QB + 1];
        #pragma unroll
        for (int r = 0; r <= ROWS_PER_QB; r++) {
            int row = i0 + r;
            a[r] = (row < RES) ? pl[row * RES + t] : 0.0f;
        }
        float na[ROWS_PER_QB + 1];
        #pragma unroll
        for (int r = 0; r <= ROWS_PER_QB; r++) {
            na[r] = __shfl_down_sync(0xffffffffu, a[r], 1);
            if ((t & 31) == 31 && t + 1 < RES) {      // lane-31 patch-up
                int row = i0 + r;
                na[r] = (row < RES) ? pl[row * RES + t + 1] : 0.0f;
            }
        }
        if (t < RES - 1) {
            #pragma unroll
            for (int r = 0; r < ROWS_PER_QB; r++) {
                int row = i0 + r;
                if (row < RES - 1)
                    g_quad[(p << 18) + (row << 9) + t] =
                        make_float4(a[r], na[r], a[r + 1], na[r + 1]);
            }
        }
        return;
    }

    // ---------------- PWL table setup (block = outer segment s) ----------------
    __shared__ float  sw1[HID], sb1[HID], ssort[HID], skink[HID];
    __shared__ float2 sab[HID];
    __shared__ float  spa[4][HID], spb[4][HID];
    __shared__ float  su[HID];
    __shared__ int    sval[HID], sm_m;
    int j = t & (HID - 1);
    int q = t >> 7;                 // 0..3
    int s = blockIdx.x;

    if (q == 0) {
        float w = w1[j], b = b1[j];
        sw1[j] = w; sb1[j] = b;
        su[j] = -b / w;
    }
    __syncthreads();
    if (q == 0) {
        float tj = su[j];
        int rank = 0;
        #pragma unroll 8
        for (int k = 0; k < HID; k++) {
            float tk = su[k];
            rank += (tk < tj) || (tk == tj && k < j);
        }
        ssort[rank] = tj;
    }
    __syncthreads();

    float segLo = (s == 0)   ? -FLT_MAX : ssort[s - 1];
    float segHi = (s == HID) ?  FLT_MAX : ssort[s];
    float Fm = (s == 0)   ? ssort[0] - 1.0f
             : (s == HID) ? ssort[HID - 1] + 1.0f
                          : 0.5f * (segLo + segHi);

    float pa = 0.0f, pb = 0.0f;
    #pragma unroll
    for (int ii = 0; ii < 32; ii++) {
        int i = q * 32 + ii;
        float wi = sw1[i], bi = sb1[i];
        bool act = fmaf(wi, Fm, bi) > 0.0f;
        float w2ij = __ldg(&w2[i * HID + j]);
        pa = fmaf(act ? wi : 0.0f, w2ij, pa);
        pb = fmaf(act ? bi : 0.0f, w2ij, pb);
    }
    spa[q][j] = pa; spb[q][j] = pb;
    __syncthreads();

    if (q == 0) {
        float alpha = (spa[0][j] + spa[1][j]) + (spa[2][j] + spa[3][j]);
        float beta  = (spb[0][j] + spb[1][j]) + (spb[2][j] + spb[3][j]) + b2[j];
        sab[j] = make_float2(alpha, beta);
        float u = -beta / alpha;
        bool valid = (alpha != 0.0f) && (u > segLo) && (u < segHi); // NaN->false
        su[j]   = valid ? u : FLT_MAX;
        sval[j] = valid ? 1 : 0;
    }
    __syncthreads();
    if (q == 0) {
        int m = 0, r = 0;
        float uj = su[j];
        #pragma unroll 8
        for (int k = 0; k < HID; k++) {
            m += sval[k];
            float uk = su[k];
            r += (uk < uj) || (uk == uj && k < j);
        }
        if (sval[j]) skink[r] = su[j];
        if (j == 0) sm_m = m;
    }
    __syncthreads();

    int nsub = sm_m + 1;
    int base = s * SLOT;
    float b3v = b3[0];
    int wid = t >> 5, lane = t & 31;

    if (t == 0) g_m[s] = sm_m;
    for (int f = nsub + t; f < SLOT; f += 512)
        g_flatT[base + f] = segHi;          // fillers keep padded array sorted

    for (int r = wid; r < nsub; r += 16) {
        float lo_r = (r == 0)        ? segLo : skink[r - 1];
        float hi_r = (r == nsub - 1) ? segHi : skink[r];
        float Fmid;
        if (lo_r == -FLT_MAX)      Fmid = hi_r - 1.0f;
        else if (hi_r == FLT_MAX)  Fmid = lo_r + 1.0f;
        else                       Fmid = 0.5f * (lo_r + hi_r);

        float A = 0.0f, B = 0.0f;
        #pragma unroll
        for (int k = lane; k < HID; k += 32) {
            float2 ab = sab[k];
            if (fmaf(ab.x, Fmid, ab.y) > 0.0f) {
                float w3k = __ldg(&w3[k]);
                A = fmaf(w3k, ab.x, A);
                B = fmaf(w3k, ab.y, B);
            }
        }
        #pragma unroll
        for (int d = 16; d; d >>= 1) {
            A += __shfl_xor_sync(0xffffffffu, A, d);
            B += __shfl_xor_sync(0xffffffffu, B, d);
        }
        if (lane == 0) {
            g_flatT[base + r]  = lo_r;
            g_flatAB[base + r] = make_float2(A, B + b3v);
        }
    }
}

// ============================================================================
// Compaction + direct-answer LUT build (1 block, 1024 threads).
//   scan counts -> compact cT/cAB; slut[e]=ub(edge(e)) over SMEM cT;
//   lutAB2[b] = cAB[s] if slut[b-1]==slut[b+1]==s (provably exact segment),
//               else bitwise sentinel + packed (lo,hi) search bounds.
// ============================================================================
__global__ void compact_lut() {
    __shared__ int   sscan[NSEG];    // inclusive scan of (m_s + 1)
    __shared__ float scT[CAP];
    __shared__ unsigned short slut[LUTE];
    int t = threadIdx.x;

    if (t < NSEG) sscan[t] = g_m[t] + 1;
    __syncthreads();
    #pragma unroll
    for (int d = 1; d < 256; d <<= 1) {
        int v = (t >= d && t < NSEG) ? sscan[t - d] : 0;
        __syncthreads();
        if (t < NSEG) sscan[t] += v;
        __syncthreads();
    }
    int K = sscan[NSEG - 1];
    if (t == 0) g_K = K;

    if (K <= CAP) {
        int wid = t >> 5, lane = t & 31;
        for (int s = wid; s < NSEG; s += 32) {
            int off = (s == 0) ? 0 : sscan[s - 1];
            int n   = sscan[s] - off;
            int base = s * SLOT;
            for (int r = lane; r < n; r += 32) {
                float tv = g_flatT[base + r];
                g_cT[off + r]  = tv;
                scT[off + r]   = tv;
                g_cAB[off + r] = g_flatAB[base + r];
            }
        }
        __syncthreads();
        // slut[e] = max{i : cT[i] <= edge(e)}
        for (int e = t; e < LUTE; e += 1024) {
            float edge = fmaf((float)(e - 1), 1.0f / LSCALE, LUT_LO);
            int lo = 0, hi = K - 1;
            while (lo < hi) {
                int mid = (lo + hi + 1) >> 1;
                if (scT[mid] <= edge) lo = mid; else hi = mid - 1;
            }
            slut[e] = (unsigned short)lo;
        }
        __syncthreads();
        // direct-answer LUT
        for (int b = t + 1; b <= NB; b += 1024) {
            int s0 = slut[b - 1];
            int s1 = slut[b + 1];
            if (s0 == s1) {
                g_lutAB2[b] = g_cAB[s0];
            } else {
                g_lutAB2[b] = make_float2(
                    __uint_as_float(SENTINEL_BITS),
                    __uint_as_float((unsigned)s0 | ((unsigned)s1 << 16)));
            }
        }
        if (t == 0) {
            float2 sent = make_float2(__uint_as_float(SENTINEL_BITS),
                                      __uint_as_float(0u | ((unsigned)(K - 1) << 16)));
            g_lutAB2[0]      = sent;
            g_lutAB2[NB + 1] = sent;
        }
    } else {
        // fallback (not expected): LUT over padded table for L2-search path
        for (int b = t; b < LUTE; b += 1024) {
            float edge = fmaf((float)(b - 1), 1.0f / LSCALE, LUT_LO);
            int lo = 0, hi = KTOT - 1;
            while (lo < hi) {
                int mid = (lo + hi + 1) >> 1;
                if (__ldg(&g_flatT[mid]) <= edge) lo = mid; else hi = mid - 1;
            }
            g_lut[b] = (unsigned short)lo;
        }
    }
}

// ============================================================================
// Main kernel: 2 points/thread. SMEM: cT (16KB, fallback search) + lutAB2
// (64KB, direct answers). Common path per point: 3 quad LDG + 1 LDS.64 + tanh.
// ============================================================================
__device__ __forceinline__ float quad_lerp(float4 q, float h, float v) {
    float bottom = fmaf(q.z - q.x, h, q.x);
    float top    = fmaf(q.w - q.y, h, q.y);
    return fmaf(top - bottom, v, bottom);
}

__device__ __forceinline__ float eval_F(float px, float py, float pz) {
    float cx = fmaf(px, 255.5f, 255.5f);   // (p+1)*0.5*511 in [0,511)
    float cy = fmaf(py, 255.5f, 255.5f);
    float cz = fmaf(pz, 255.5f, 255.5f);
    int ix = min((int)cx, RES - 2);
    int iy = min((int)cy, RES - 2);
    int iz = min((int)cz, RES - 2);
    float hx = cx - (float)ix;
    float hy = cy - (float)iy;
    float hz = cz - (float)iz;

    float4 qxy = __ldg(&g_quad[           (ix << 9) + iy]);
    float4 qyz = __ldg(&g_quad[(1 << 18) + (iy << 9) + iz]);
    float4 qxz = __ldg(&g_quad[(2 << 18) + (ix << 9) + iz]);

    return quad_lerp(qxy, hx, hy)
         + quad_lerp(qxz, hx, hz)
         + quad_lerp(qyz, hy, hz);
}

// per-point evaluate on the compact path
__device__ __forceinline__ float eval_out(float F, int Km1, const float* sT,
                                          const float2* sLutAB) {
    float tb = fmaf(F - LUT_LO, LSCALE, 0.0f);
    int bq = min(max((int)tb, 0), NB - 1) + 1;      // 1 .. NB
    float2 e = sLutAB[bq];
    bool inr = (F >= LUT_LO) && (F < LUT_HI);
    float Av = e.x, Bv = e.y;
    if (!inr || (__float_as_uint(e.x) == SENTINEL_BITS)) {
        int lo, hi;
        if (inr) {
            unsigned p = __float_as_uint(e.y);
            lo = (int)(p & 0xFFFFu);
            hi = (int)(p >> 16);
        } else {
            lo = 0; hi = Km1;
        }
        while (lo < hi) {
            int mid = (lo + hi + 1) >> 1;
            bool le = sT[mid] <= F;
            lo = le ? mid : lo;
            hi = le ? hi  : mid - 1;
        }
        float2 ab = __ldg(&g_cAB[lo]);
        Av = ab.x; Bv = ab.y;
    }
    float r;
    asm("tanh.approx.f32 %0, %1;" : "=f"(r) : "f"(fmaf(Av, F, Bv)));
    return r;
}

__global__ __launch_bounds__(1024, 1)
void neusdf_main(const float* __restrict__ points,
                 float* __restrict__ out, int N) {
    extern __shared__ float sm[];
    float*  sT     = sm;                          // [CAP]   16,384 B
    float2* sLutAB = (float2*)(sm + CAP);         // [NB+2]  65,552 B
    __shared__ int sK;
    if (threadIdx.x == 0) sK = g_K;
    __syncthreads();
    int K = sK;
    bool compact = (K <= CAP);

    if (compact) {
        for (int i = threadIdx.x; i < K; i += 1024) sT[i] = g_cT[i];
        for (int i = threadIdx.x; i < NB + 2; i += 1024) sLutAB[i] = g_lutAB2[i];
    }
    __syncthreads();

    const float2* pp = (const float2*)points;
    float2*       op = (float2*)out;
    int G = N >> 1;
    int gstride = gridDim.x * blockDim.x;

    if (compact) {
        int Km1 = K - 1;
        for (int g = blockIdx.x * blockDim.x + threadIdx.x; g < G; g += gstride) {
            float2 u = pp[3 * g + 0];
            float2 v = pp[3 * g + 1];
            float2 w = pp[3 * g + 2];
            float F0 = eval_F(u.x, u.y, v.x);
            float F1 = eval_F(v.y, w.x, w.y);
            float2 o;
            o.x = eval_out(F0, Km1, sT, sLutAB);
            o.y = eval_out(F1, Km1, sT, sLutAB);
            op[g] = o;
        }
        if ((N & 1) && blockIdx.x == 0 && threadIdx.x == 0) {
            int i = N - 1;
            float Ft = eval_F(points[3*i], points[3*i+1], points[3*i+2]);
            out[i] = eval_out(Ft, Km1, sT, sLutAB);
        }
    } else {
        // fallback (K > CAP, not expected): padded table + g_lut, all in L2
        for (int g = blockIdx.x * blockDim.x + threadIdx.x; g < G; g += gstride) {
            float2 u = pp[3 * g + 0];
            float2 v = pp[3 * g + 1];
            float2 w = pp[3 * g + 2];
            float F[2] = { eval_F(u.x, u.y, v.x), eval_F(v.y, w.x, w.y) };
            float o2[2];
            #pragma unroll
            for (int k = 0; k < 2; k++) {
                float tb = fmaf(F[k] - LUT_LO, LSCALE, 0.0f);
                int bq = min(max((int)tb, 0), NB - 1) + 1;
                int lo = (int)__ldg(&g_lut[bq - 1]);
                int hi = (int)__ldg(&g_lut[bq + 1]);
                if (F[k] <  LUT_LO) lo = 0;
                if (F[k] >= LUT_HI) hi = KTOT - 1;
                while (lo < hi) {
                    int mid = (lo + hi + 1) >> 1;
                    bool le = __ldg(&g_flatT[mid]) <= F[k];
                    lo = le ? mid : lo;
                    hi = le ? hi  : mid - 1;
                }
                float2 ab = __ldg(&g_flatAB[lo]);
                asm("tanh.approx.f32 %0, %1;" : "=f"(o2[k]) : "f"(fmaf(ab.x, F[k], ab.y)));
            }
            op[g] = make_float2(o2[0], o2[1]);
        }
    }
}

// ============================================================================
extern "C" void kernel_launch(void* const* d_in, const int* in_sizes, int n_in,
                              void* d_out, int out_size) {
    const float* points = (const float*)d_in[0];
    const float* xy     = (const float*)d_in[1];
    const float* yz     = (const float*)d_in[2];
    const float* xz     = (const float*)d_in[3];
    const float* w1     = (const float*)d_in[4];
    const float* b1     = (const float*)d_in[5];
    const float* w2     = (const float*)d_in[6];
    const float* b2     = (const float*)d_in[7];
    const float* w3     = (const float*)d_in[8];
    const float* b3     = (const float*)d_in[9];
    int N = in_sizes[0] / 3;

    setup_all  <<<NSEG + QBLOCKS, 512>>>(w1, b1, w2, b2, w3, b3, xy, yz, xz);
    compact_lut<<<1, 1024>>>();

    size_t smem = sizeof(float) * CAP + sizeof(float2) * (NB + 2);
    cudaFuncSetAttribute(neusdf_main,
                         cudaFuncAttributeMaxDynamicSharedMemorySize,
                         (int)smem);

    int nsm = 148;
    cudaDeviceGetAttribute(&nsm, cudaDevAttrMultiProcessorCount, 0);

    neusdf_main<<<nsm, 1024, smem>>>(points, (float*)d_out, N);
}

// round 17
// speedup vs baseline: 1.2393x; 1.2393x over previous
#include <cuda_runtime.h>
#include <math.h>
#include <float.h>

#define RES   512
#define HID   128
#define NSEG  (HID + 1)            // 129 outer segments
#define SLOT  130                  // fixed slots per outer segment (padded layout)
#define KTOT  (NSEG * SLOT)        // 16770 padded final segments
#define ROWS_PER_QB 4
#define QROWB ((RES - 1 + ROWS_PER_QB - 1) / ROWS_PER_QB)   // 128 row-blocks/plane
#define QBLOCKS (3 * QROWB)        // 384 quad-builder blocks

// ---- sampled output table over F in [LUT_LO, LUT_HI], NB bins ----
#define NB      16384
#define LUT_LO  (-12.0f)
#define LUT_HI  ( 12.0f)
#define LSCALE  (16384.0f / 24.0f) // NB / (HI - LO)
#define DELTA   (24.0f / 16384.0f) // bin width

// ---------------- persistent device tables (rebuilt every launch) ----------
__device__ float  g_flatT[KTOT];            // padded non-decreasing breakpoints
__device__ float2 g_flatAB[KTOT];           // padded (A, B+b3)  (fallback path)
__device__ float  g_lutY[NB + 1];           // sampled out(F_e) at edges e=0..NB
__device__ float4 g_quad[3 * 512 * 512];    // 2x2 corner quads per plane (12MB)

// ============================================================================
// Fused setup: blocks [0,129) build PWL tables + scatter the sampled-output
// table; blocks [129,129+384) build the quad layout, 4 quad-rows per block.
// ============================================================================
__global__ void setup_all(const float* __restrict__ w1,
                          const float* __restrict__ b1,
                          const float* __restrict__ w2,
                          const float* __restrict__ b2,
                          const float* __restrict__ w3,
                          const float* __restrict__ b3,
                          const float* __restrict__ xy,
                          const float* __restrict__ yz,
                          const float* __restrict__ xz) {
    int t = threadIdx.x;

    if (blockIdx.x >= NSEG) {
        // ---------------- quad builder: 4 rows per block ----------------
        int b = blockIdx.x - NSEG;
        int p = b / QROWB;
        int i0 = (b % QROWB) * ROWS_PER_QB;
        const float* pl = (p == 0) ? xy : (p == 1) ? yz : xz;

        float a[ROWS_PER_QB + 1];
        #pragma unroll
        for (int r = 0; r <= ROWS_PER_QB; r++) {
            int row = i0 + r;
            a[r] = (row < RES) ? pl[row * RES + t] : 0.0f;
        }
        float na[ROWS_PER_QB + 1];
        #pragma unroll
        for (int r = 0; r <= ROWS_PER_QB; r++) {
            na[r] = __shfl_down_sync(0xffffffffu, a[r], 1);
            if ((t & 31) == 31 && t + 1 < RES) {      // lane-31 patch-up
                int row = i0 + r;
                na[r] = (row < RES) ? pl[row * RES + t + 1] : 0.0f;
            }
        }
        if (t < RES - 1) {
            #pragma unroll
            for (int r = 0; r < ROWS_PER_QB; r++) {
                int row = i0 + r;
                if (row < RES - 1)
                    g_quad[(p << 18) + (row << 9) + t] =
                        make_float4(a[r], na[r], a[r + 1], na[r + 1]);
            }
        }
        return;
    }

    // ---------------- PWL table setup (block = outer segment s) ----------------
    __shared__ float  sw1[HID], sb1[HID], ssort[HID], skink[HID];
    __shared__ float2 sab[HID];
    __shared__ float  spa[4][HID], spb[4][HID];
    __shared__ float  su[HID];
    __shared__ int    sval[HID], sm_m;
    int j = t & (HID - 1);
    int q = t >> 7;                 // 0..3
    int s = blockIdx.x;

    if (q == 0) {
        float w = w1[j], b = b1[j];
        sw1[j] = w; sb1[j] = b;
        su[j] = -b / w;
    }
    __syncthreads();
    if (q == 0) {
        float tj = su[j];
        int rank = 0;
        #pragma unroll 8
        for (int k = 0; k < HID; k++) {
            float tk = su[k];
            rank += (tk < tj) || (tk == tj && k < j);
        }
        ssort[rank] = tj;
    }
    __syncthreads();

    float segLo = (s == 0)   ? -FLT_MAX : ssort[s - 1];
    float segHi = (s == HID) ?  FLT_MAX : ssort[s];
    float Fm = (s == 0)   ? ssort[0] - 1.0f
             : (s == HID) ? ssort[HID - 1] + 1.0f
                          : 0.5f * (segLo + segHi);

    float pa = 0.0f, pb = 0.0f;
    #pragma unroll
    for (int ii = 0; ii < 32; ii++) {
        int i = q * 32 + ii;
        float wi = sw1[i], bi = sb1[i];
        bool act = fmaf(wi, Fm, bi) > 0.0f;
        float w2ij = __ldg(&w2[i * HID + j]);
        pa = fmaf(act ? wi : 0.0f, w2ij, pa);
        pb = fmaf(act ? bi : 0.0f, w2ij, pb);
    }
    spa[q][j] = pa; spb[q][j] = pb;
    __syncthreads();

    if (q == 0) {
        float alpha = (spa[0][j] + spa[1][j]) + (spa[2][j] + spa[3][j]);
        float beta  = (spb[0][j] + spb[1][j]) + (spb[2][j] + spb[3][j]) + b2[j];
        sab[j] = make_float2(alpha, beta);
        float u = -beta / alpha;
        bool valid = (alpha != 0.0f) && (u > segLo) && (u < segHi); // NaN->false
        su[j]   = valid ? u : FLT_MAX;
        sval[j] = valid ? 1 : 0;
    }
    __syncthreads();
    if (q == 0) {
        int m = 0, r = 0;
        float uj = su[j];
        #pragma unroll 8
        for (int k = 0; k < HID; k++) {
            m += sval[k];
            float uk = su[k];
            r += (uk < uj) || (uk == uj && k < j);
        }
        if (sval[j]) skink[r] = su[j];
        if (j == 0) sm_m = m;
    }
    __syncthreads();

    int nsub = sm_m + 1;
    int base = s * SLOT;
    float b3v = b3[0];
    int wid = t >> 5, lane = t & 31;

    for (int f = nsub + t; f < SLOT; f += 512)
        g_flatT[base + f] = segHi;          // fillers keep padded array sorted

    for (int r = wid; r < nsub; r += 16) {
        float lo_r = (r == 0)        ? segLo : skink[r - 1];
        float hi_r = (r == nsub - 1) ? segHi : skink[r];
        float Fmid;
        if (lo_r == -FLT_MAX)      Fmid = hi_r - 1.0f;
        else if (hi_r == FLT_MAX)  Fmid = lo_r + 1.0f;
        else                       Fmid = 0.5f * (lo_r + hi_r);

        float A = 0.0f, B = 0.0f;
        #pragma unroll
        for (int k = lane; k < HID; k += 32) {
            float2 ab = sab[k];
            if (fmaf(ab.x, Fmid, ab.y) > 0.0f) {
                float w3k = __ldg(&w3[k]);
                A = fmaf(w3k, ab.x, A);
                B = fmaf(w3k, ab.y, B);
            }
        }
        #pragma unroll
        for (int d = 16; d; d >>= 1) {
            A += __shfl_xor_sync(0xffffffffu, A, d);
            B += __shfl_xor_sync(0xffffffffu, B, d);
        }
        float Bfull = B + b3v;
        if (lane == 0) {
            g_flatT[base + r]  = lo_r;
            g_flatAB[base + r] = make_float2(A, Bfull);
        }

        // ---- sampled-output scatter: edges e with lo_r <= F_e < hi_r.
        //      Adjacent sub-intervals compute the shared e-boundary from the
        //      SAME kink value with identical fp ops -> exact tiling. ----
        float v0 = (lo_r - LUT_LO) * LSCALE;
        float v1 = (hi_r - LUT_LO) * LSCALE;
        v0 = fminf(fmaxf(v0, 0.0f), (float)(NB + 1));   // -inf/+inf safe
        v1 = fminf(fmaxf(v1, 0.0f), (float)(NB + 1));
        int e0 = (int)ceilf(v0);
        int e1 = (int)ceilf(v1);
        for (int e = e0 + lane; e < e1 && e <= NB; e += 32) {
            float Fe = fmaf((float)e, DELTA, LUT_LO);
            g_lutY[e] = tanhf(fmaf(A, Fe, Bfull));
        }
    }
}

// ============================================================================
// Main kernel: 2 points/thread. SMEM = sampled table sY[NB+1] (65.5KB).
// Per point: 3 quad LDG.128 + 2 scalar LDS + 1 lerp FMA. No search, no tanh.
// ============================================================================
__device__ __forceinline__ float quad_lerp(float4 q, float h, float v) {
    float bottom = fmaf(q.z - q.x, h, q.x);
    float top    = fmaf(q.w - q.y, h, q.y);
    return fmaf(top - bottom, v, bottom);
}

__device__ __forceinline__ float eval_F(float px, float py, float pz) {
    float cx = fmaf(px, 255.5f, 255.5f);   // (p+1)*0.5*511 in [0,511)
    float cy = fmaf(py, 255.5f, 255.5f);
    float cz = fmaf(pz, 255.5f, 255.5f);
    int ix = min((int)cx, RES - 2);
    int iy = min((int)cy, RES - 2);
    int iz = min((int)cz, RES - 2);
    float hx = cx - (float)ix;
    float hy = cy - (float)iy;
    float hz = cz - (float)iz;

    float4 qxy = __ldg(&g_quad[           (ix << 9) + iy]);
    float4 qyz = __ldg(&g_quad[(1 << 18) + (iy << 9) + iz]);
    float4 qxz = __ldg(&g_quad[(2 << 18) + (ix << 9) + iz]);

    return quad_lerp(qxy, hx, hy)
         + quad_lerp(qxz, hx, hz)
         + quad_lerp(qyz, hy, hz);
}

// rare exact fallback for |F| outside the sampled range (~never taken)
__device__ __noinline__ float eval_fallback(float F) {
    int lo = 0, hi = KTOT - 1;
    while (lo < hi) {
        int mid = (lo + hi + 1) >> 1;
        bool le = __ldg(&g_flatT[mid]) <= F;
        lo = le ? mid : lo;
        hi = le ? hi  : mid - 1;
    }
    float2 ab = __ldg(&g_flatAB[lo]);
    float r;
    asm("tanh.approx.f32 %0, %1;" : "=f"(r) : "f"(fmaf(ab.x, F, ab.y)));
    return r;
}

__device__ __forceinline__ float eval_out(float F, const float* sY) {
    if (F >= LUT_LO && F < LUT_HI) {
        float tb = (F - LUT_LO) * LSCALE;
        int b = min((int)tb, NB - 1);
        float fr = tb - (float)b;
        float y0 = sY[b];
        float y1 = sY[b + 1];
        return fmaf(y1 - y0, fr, y0);
    }
    return eval_fallback(F);
}

__global__ __launch_bounds__(1024, 1)
void neusdf_main(const float* __restrict__ points,
                 float* __restrict__ out, int N) {
    extern __shared__ float sY[];                 // [NB+1]  65,540 B

    for (int i = threadIdx.x; i <= NB; i += 1024) sY[i] = g_lutY[i];
    __syncthreads();

    const float2* pp = (const float2*)points;
    float2*       op = (float2*)out;
    int G = N >> 1;
    int gstride = gridDim.x * blockDim.x;

    for (int g = blockIdx.x * blockDim.x + threadIdx.x; g < G; g += gstride) {
        float2 u = pp[3 * g + 0];
        float2 v = pp[3 * g + 1];
        float2 w = pp[3 * g + 2];
        float F0 = eval_F(u.x, u.y, v.x);
        float F1 = eval_F(v.y, w.x, w.y);
        float2 o;
        o.x = eval_out(F0, sY);
        o.y = eval_out(F1, sY);
        op[g] = o;
    }
    if ((N & 1) && blockIdx.x == 0 && threadIdx.x == 0) {
        int i = N - 1;
        float Ft = eval_F(points[3*i], points[3*i+1], points[3*i+2]);
        out[i] = eval_out(Ft, sY);
    }
}

// ============================================================================
extern "C" void kernel_launch(void* const* d_in, const int* in_sizes, int n_in,
                              void* d_out, int out_size) {
    const float* points = (const float*)d_in[0];
    const float* xy     = (const float*)d_in[1];
    const float* yz     = (const float*)d_in[2];
    const float* xz     = (const float*)d_in[3];
    const float* w1     = (const float*)d_in[4];
    const float* b1     = (const float*)d_in[5];
    const float* w2     = (const float*)d_in[6];
    const float* b2     = (const float*)d_in[7];
    const float* w3     = (const float*)d_in[8];
    const float* b3     = (const float*)d_in[9];
    int N = in_sizes[0] / 3;

    setup_all<<<NSEG + QBLOCKS, 512>>>(w1, b1, w2, b2, w3, b3, xy, yz, xz);

    size_t smem = sizeof(float) * (NB + 1);
    cudaFuncSetAttribute(neusdf_main,
                         cudaFuncAttributeMaxDynamicSharedMemorySize,
                         (int)smem);

    int nsm = 148;
    cudaDeviceGetAttribute(&nsm, cudaDevAttrMultiProcessorCount, 0);

    neusdf_main<<<nsm, 1024, smem>>>(points, (float*)d_out, N);
}